// round 8
// baseline (speedup 1.0000x reference)
#include <cuda_runtime.h>
#include <cstdint>

// ---------------------------------------------------------------------------
// BMM_AB_I8_E_F32: C[b,m,n] = alpha * sum_k a[b,m,k]*b[b,k,n]
// B=16, M=1024, K=4096, N=4096.
//
// R2: PTX target sm_103 (no 'a') -> no tcgen05; legacy mma.sync.m16n8k32.s8.
// R6: inputs serialized as int32 -> convert to int8 scratch first.
// R7: GEMM ~3.7ms, no ncu (capture hit conv). This round: remove register
//     pressure (bw[] gone), all-gmem-async 3-stage cp.async pipeline with
//     SMEM->SMEM B transpose; GEMM split into 4 launches so ncu -s 5 lands
//     on a GEMM.
// ---------------------------------------------------------------------------

#define BATCH   16
#define MDIM    1024
#define KDIM    4096
#define NDIM    4096

#define MT      128
#define NT      128
#define KT      64            // K bytes per pipeline chunk
#define KCHUNKS (KDIM / KT)   // 64
#define THREADS 256
#define NSTAGE  3

#define A_STRIDE 80                     // bytes per m-row in SMEM
#define A_STAGE  (128 * A_STRIDE)       // 10240
#define BRAW_STAGE (64 * 128)           // 8192  raw [k][n] chunk
#define B_WORDS  132                    // transposed k-word row stride (words)
#define BT_BYTES (16 * B_WORDS * 4)     // 8448

#define OFF_A    0
#define OFF_BRAW (NSTAGE * A_STAGE)                 // 30720
#define OFF_BT   (OFF_BRAW + NSTAGE * BRAW_STAGE)   // 55296
#define SMEM_TOTAL (OFF_BT + BT_BYTES)              // 63744

#define A_ELEMS ((size_t)BATCH * MDIM * KDIM)   // 67108864
#define B_ELEMS ((size_t)BATCH * KDIM * NDIM)   // 268435456

__device__ int8_t g_a8[A_ELEMS];
__device__ int8_t g_b8[B_ELEMS];

// ---------------- int32 -> int8 conversion ----------------
__device__ __forceinline__ uint32_t pack4(int4 x) {
    uint32_t lo = __byte_perm((uint32_t)x.x, (uint32_t)x.y, 0x0040);
    uint32_t hi = __byte_perm((uint32_t)x.z, (uint32_t)x.w, 0x0040);
    return __byte_perm(lo, hi, 0x5410);
}

__global__ void __launch_bounds__(256)
conv_kernel(const int4* __restrict__ src, uint4* __restrict__ dst, long n16) {
    const long stride = (long)gridDim.x * blockDim.x;
    for (long i = (long)blockIdx.x * blockDim.x + threadIdx.x; i < n16; i += stride) {
        const int4 x0 = src[i * 4 + 0];
        const int4 x1 = src[i * 4 + 1];
        const int4 x2 = src[i * 4 + 2];
        const int4 x3 = src[i * 4 + 3];
        uint4 v;
        v.x = pack4(x0); v.y = pack4(x1); v.z = pack4(x2); v.w = pack4(x3);
        dst[i] = v;
    }
}

// ---------------- GEMM helpers ----------------
__device__ __forceinline__ uint32_t smem_u32(const void* p) {
    uint32_t a;
    asm("{ .reg .u64 t; cvta.to.shared.u64 t, %1; cvt.u32.u64 %0, t; }"
        : "=r"(a) : "l"(p));
    return a;
}

__device__ __forceinline__ void cpa16(uint32_t dst, const void* src) {
    asm volatile("cp.async.cg.shared.global [%0], [%1], 16;" :: "r"(dst), "l"(src));
}

__device__ __forceinline__ void ldmA(uint32_t a[4], uint32_t addr) {
    asm volatile("ldmatrix.sync.aligned.m8n8.x4.shared.b16 {%0,%1,%2,%3}, [%4];"
                 : "=r"(a[0]), "=r"(a[1]), "=r"(a[2]), "=r"(a[3]) : "r"(addr));
}

__device__ __forceinline__ uint32_t lds32(uint32_t addr) {
    uint32_t v;
    asm volatile("ld.shared.b32 %0, [%1];" : "=r"(v) : "r"(addr));
    return v;
}

__device__ __forceinline__ void mma_s8(int c[4], const uint32_t a[4],
                                       uint32_t b0, uint32_t b1) {
    asm volatile(
        "mma.sync.aligned.m16n8k32.row.col.s32.s8.s8.s32 "
        "{%0,%1,%2,%3}, {%4,%5,%6,%7}, {%8,%9}, {%0,%1,%2,%3};"
        : "+r"(c[0]), "+r"(c[1]), "+r"(c[2]), "+r"(c[3])
        : "r"(a[0]), "r"(a[1]), "r"(a[2]), "r"(a[3]), "r"(b0), "r"(b1));
}

__global__ void __launch_bounds__(THREADS, 2)
bmm_i8_kernel(const float* __restrict__ alpha_p, float* __restrict__ out,
              int batch0)
{
    extern __shared__ char smem[];
    const uint32_t sbase = smem_u32(smem);

    const int tid  = threadIdx.x;
    const int wid  = tid >> 5;
    const int lane = tid & 31;

    // 256 tiles per batch (8 m x 32 n); this launch covers 4 batches
    const int bid   = blockIdx.x;
    const int batch = batch0 + (bid >> 8);
    const int rem   = bid & 255;
    const int m0    = (rem >> 5) * MT;
    const int n0    = (rem & 31) * NT;

    const int8_t* aB = g_a8 + (size_t)batch * MDIM * KDIM + (size_t)m0 * KDIM;
    const int8_t* bB = g_b8 + (size_t)batch * KDIM * NDIM + n0;
    float* outB = out + (size_t)batch * MDIM * NDIM;

    const int wm = wid >> 2;
    const int wn = wid & 3;

    // cp.async indices
    const int ar0 = tid >> 2;             // A rows 0..63 (+64)
    const int ac0 = (tid & 3) << 4;
    const int br0 = tid >> 3;             // Braw rows 0..31 (+32)
    const int bc0 = (tid & 7) << 4;
    // transpose indices
    const int nb  = tid & 31;
    const int kb0 = tid >> 5;

    int cacc[4][4][4];
#pragma unroll
    for (int i = 0; i < 4; i++)
#pragma unroll
        for (int j = 0; j < 4; j++)
#pragma unroll
            for (int r = 0; r < 4; r++) cacc[i][j][r] = 0;

    auto issue_chunk = [&](int chunk, int stg) {
        const int kk = chunk * KT;
        const uint32_t sA = sbase + OFF_A + stg * A_STAGE;
        cpa16(sA + ar0 * A_STRIDE + ac0,        aB + (size_t)ar0 * KDIM + kk + ac0);
        cpa16(sA + (ar0 + 64) * A_STRIDE + ac0, aB + (size_t)(ar0 + 64) * KDIM + kk + ac0);
        const uint32_t sR = sbase + OFF_BRAW + stg * BRAW_STAGE;
        cpa16(sR + br0 * 128 + bc0,        bB + (size_t)(kk + br0) * NDIM + bc0);
        cpa16(sR + (br0 + 32) * 128 + bc0, bB + (size_t)(kk + br0 + 32) * NDIM + bc0);
    };

    auto transposeB = [&](int stg) {
        const uint32_t src = sbase + OFF_BRAW + stg * BRAW_STAGE;
        uint32_t* dst = reinterpret_cast<uint32_t*>(smem + OFF_BT);
#pragma unroll
        for (int t = 0; t < 2; t++) {
            const int kb = kb0 + t * 8;
            const uint32_t rb = src + (uint32_t)(kb * 4) * 128 + nb * 4;
            uint32_t a0 = lds32(rb);
            uint32_t a1 = lds32(rb + 128);
            uint32_t a2 = lds32(rb + 256);
            uint32_t a3 = lds32(rb + 384);
            uint32_t t0 = __byte_perm(a0, a1, 0x5140);
            uint32_t t1 = __byte_perm(a0, a1, 0x7362);
            uint32_t t2 = __byte_perm(a2, a3, 0x5140);
            uint32_t t3 = __byte_perm(a2, a3, 0x7362);
            uint4 v;
            v.x = __byte_perm(t0, t2, 0x5410);
            v.y = __byte_perm(t0, t2, 0x7632);
            v.z = __byte_perm(t1, t3, 0x5410);
            v.w = __byte_perm(t1, t3, 0x7632);
            *reinterpret_cast<uint4*>(dst + kb * B_WORDS + nb * 4) = v;
        }
    };

    auto compute = [&](int stg) {
        const uint32_t baseA = sbase + OFF_A + stg * A_STAGE;
        const uint32_t* sb = reinterpret_cast<const uint32_t*>(smem + OFF_BT);
        const int mrow = wm * 64 + (lane & 15);
        const int khl  = lane >> 4;
#pragma unroll
        for (int ks = 0; ks < 2; ks++) {
            uint32_t af[4][4];
#pragma unroll
            for (int mi = 0; mi < 4; mi++)
                ldmA(af[mi], baseA + (uint32_t)(mrow + mi * 16) * A_STRIDE
                                   + (uint32_t)(ks * 2 + khl) * 16);
            uint32_t bf[4][2];
#pragma unroll
            for (int ni = 0; ni < 4; ni++) {
                const int nl = wn * 32 + ni * 8 + (lane >> 2);
                const int kwb = ks * 8 + (lane & 3);
                bf[ni][0] = sb[(kwb)     * B_WORDS + nl];
                bf[ni][1] = sb[(kwb + 4) * B_WORDS + nl];
            }
#pragma unroll
            for (int ni = 0; ni < 4; ni++)
#pragma unroll
                for (int mi = 0; mi < 4; mi++)
                    mma_s8(cacc[mi][ni], af[mi], bf[ni][0], bf[ni][1]);
        }
    };

    // ---- prologue: chunks 0 and 1 in flight ----
    issue_chunk(0, 0);
    asm volatile("cp.async.commit_group;" ::: "memory");
    issue_chunk(1, 1);
    asm volatile("cp.async.commit_group;" ::: "memory");

    // ---- mainloop ----
    int stg = 0;
    for (int i = 0; i < KCHUNKS; i++) {
        if (i + 1 < KCHUNKS)
            asm volatile("cp.async.wait_group 1;" ::: "memory");
        else
            asm volatile("cp.async.wait_group 0;" ::: "memory");
        __syncthreads();   // chunk i visible to all; prior compute/transpose done

        if (i + 2 < KCHUNKS) {
            // stage (i+2)%3 held chunk i-1, consumed before the sync above
            int fstg = stg + 2; if (fstg >= NSTAGE) fstg -= NSTAGE;
            issue_chunk(i + 2, fstg);
            asm volatile("cp.async.commit_group;" ::: "memory");
        }

        transposeB(stg);
        __syncthreads();
        compute(stg);

        if (++stg == NSTAGE) stg = 0;
    }

    // ---- epilogue ----
    const float alpha = *alpha_p;
#pragma unroll
    for (int mi = 0; mi < 4; mi++) {
#pragma unroll
        for (int ni = 0; ni < 4; ni++) {
            const int row = m0 + wm * 64 + mi * 16 + (lane >> 2);
            const int col = n0 + wn * 32 + ni * 8 + 2 * (lane & 3);
            float2 v0, v1;
            v0.x = (float)cacc[mi][ni][0] * alpha;
            v0.y = (float)cacc[mi][ni][1] * alpha;
            v1.x = (float)cacc[mi][ni][2] * alpha;
            v1.y = (float)cacc[mi][ni][3] * alpha;
            *reinterpret_cast<float2*>(outB + (size_t)row * NDIM + col) = v0;
            *reinterpret_cast<float2*>(outB + (size_t)(row + 8) * NDIM + col) = v1;
        }
    }
}

extern "C" void kernel_launch(void* const* d_in, const int* in_sizes, int n_in,
                              void* d_out, int out_size) {
    const int* a32 = (const int*)d_in[0];
    const int* b32 = (const int*)d_in[1];
    const float* alpha = (const float*)(n_in > 2 ? d_in[2] : d_in[1]);
    for (int i = 0; i < n_in; i++) {
        const long long sz = in_sizes[i];
        if (sz == (long long)A_ELEMS)      a32 = (const int*)d_in[i];
        else if (sz == (long long)B_ELEMS) b32 = (const int*)d_in[i];
        else if (sz == 1)                  alpha = (const float*)d_in[i];
    }
    float* out = (float*)d_out;

    int8_t* a8 = nullptr;
    int8_t* b8 = nullptr;
    cudaGetSymbolAddress((void**)&a8, g_a8);
    cudaGetSymbolAddress((void**)&b8, g_b8);

    static int smem_set = 0;
    if (!smem_set) {
        cudaFuncSetAttribute(bmm_i8_kernel,
                             cudaFuncAttributeMaxDynamicSharedMemorySize, SMEM_TOTAL);
        smem_set = 1;
    }

    // Pass 1: int32 -> int8 (HBM-bound, near roofline already)
    conv_kernel<<<2048, 256>>>((const int4*)a32, (uint4*)a8, (long)(A_ELEMS / 16));
    conv_kernel<<<2048, 256>>>((const int4*)b32, (uint4*)b8, (long)(B_ELEMS / 16));

    // Pass 2: GEMM in 4 launches (4 batches each) so ncu -s 5 captures a GEMM
    const int grid = 4 * (MDIM / MT) * (NDIM / NT);  // 1024 CTAs per launch
    for (int g = 0; g < 4; g++)
        bmm_i8_kernel<<<grid, THREADS, SMEM_TOTAL>>>(alpha, out, g * 4);
}

// round 9
// speedup vs baseline: 1.1548x; 1.1548x over previous
#include <cuda_runtime.h>
#include <cstdint>

// ---------------------------------------------------------------------------
// BMM_AB_I8_E_F32: C[b,m,n] = alpha * sum_k a[b,m,k]*b[b,k,n]
// B=16, M=1024, K=4096, N=4096.
//
// R2: PTX target sm_103 (no 'a') -> no tcgen05; legacy mma.sync only.
// R6: inputs serialized int32 -> int8 scratch conversion pre-pass.
// R8 ncu: legacy IMMA pipe = 90.5% busy at ~242 MACs/cyc/SM (peak ~267);
//         fma/alu pipes idle. The legacy tensor path is the hard wall.
// R9: HYBRID. Per 64B K-chunk: tensor pipe (mma.sync m16n8k32) computes
//     k[0:32), dp4a on the idle fma/alu pipes computes k[32:64), both
//     accumulating into the SAME per-thread C fragments (exact int32).
//     If IDP rt=2, the two engines are equal-rate -> ~2x GEMM speedup.
// ---------------------------------------------------------------------------

#define BATCH   16
#define MDIM    1024
#define KDIM    4096
#define NDIM    4096

#define MT      128
#define NT      128
#define KT      64            // K bytes per pipeline chunk
#define KCHUNKS (KDIM / KT)   // 64
#define THREADS 256
#define NSTAGE  3

#define A_STRIDE 80                     // bytes per m-row in SMEM
#define A_STAGE  (128 * A_STRIDE)       // 10240
#define BRAW_STAGE (64 * 128)           // 8192  raw [k][n] chunk
#define B_WORDS  132                    // transposed k-word row stride (words)
#define BT_BYTES (16 * B_WORDS * 4)     // 8448

#define OFF_A    0
#define OFF_BRAW (NSTAGE * A_STAGE)                 // 30720
#define OFF_BT   (OFF_BRAW + NSTAGE * BRAW_STAGE)   // 55296
#define SMEM_TOTAL (OFF_BT + BT_BYTES)              // 63744

#define A_ELEMS ((size_t)BATCH * MDIM * KDIM)   // 67108864
#define B_ELEMS ((size_t)BATCH * KDIM * NDIM)   // 268435456

__device__ int8_t g_a8[A_ELEMS];
__device__ int8_t g_b8[B_ELEMS];

// ---------------- int32 -> int8 conversion ----------------
__device__ __forceinline__ uint32_t pack4(int4 x) {
    uint32_t lo = __byte_perm((uint32_t)x.x, (uint32_t)x.y, 0x0040);
    uint32_t hi = __byte_perm((uint32_t)x.z, (uint32_t)x.w, 0x0040);
    return __byte_perm(lo, hi, 0x5410);
}

__global__ void __launch_bounds__(256)
conv_kernel(const int4* __restrict__ src, uint4* __restrict__ dst, long n16) {
    const long stride = (long)gridDim.x * blockDim.x;
    for (long i = (long)blockIdx.x * blockDim.x + threadIdx.x; i < n16; i += stride) {
        const int4 x0 = src[i * 4 + 0];
        const int4 x1 = src[i * 4 + 1];
        const int4 x2 = src[i * 4 + 2];
        const int4 x3 = src[i * 4 + 3];
        uint4 v;
        v.x = pack4(x0); v.y = pack4(x1); v.z = pack4(x2); v.w = pack4(x3);
        dst[i] = v;
    }
}

// ---------------- GEMM helpers ----------------
__device__ __forceinline__ uint32_t smem_u32(const void* p) {
    uint32_t a;
    asm("{ .reg .u64 t; cvta.to.shared.u64 t, %1; cvt.u32.u64 %0, t; }"
        : "=r"(a) : "l"(p));
    return a;
}

__device__ __forceinline__ void cpa16(uint32_t dst, const void* src) {
    asm volatile("cp.async.cg.shared.global [%0], [%1], 16;" :: "r"(dst), "l"(src));
}

__device__ __forceinline__ void ldmA(uint32_t a[4], uint32_t addr) {
    asm volatile("ldmatrix.sync.aligned.m8n8.x4.shared.b16 {%0,%1,%2,%3}, [%4];"
                 : "=r"(a[0]), "=r"(a[1]), "=r"(a[2]), "=r"(a[3]) : "r"(addr));
}

__device__ __forceinline__ uint32_t lds32(uint32_t addr) {
    uint32_t v;
    asm volatile("ld.shared.b32 %0, [%1];" : "=r"(v) : "r"(addr));
    return v;
}

__device__ __forceinline__ uint2 lds64(uint32_t addr) {
    uint2 v;
    asm volatile("ld.shared.v2.b32 {%0,%1}, [%2];" : "=r"(v.x), "=r"(v.y) : "r"(addr));
    return v;
}

__device__ __forceinline__ void mma_s8(int c[4], const uint32_t a[4],
                                       uint32_t b0, uint32_t b1) {
    asm volatile(
        "mma.sync.aligned.m16n8k32.row.col.s32.s8.s8.s32 "
        "{%0,%1,%2,%3}, {%4,%5,%6,%7}, {%8,%9}, {%0,%1,%2,%3};"
        : "+r"(c[0]), "+r"(c[1]), "+r"(c[2]), "+r"(c[3])
        : "r"(a[0]), "r"(a[1]), "r"(a[2]), "r"(a[3]), "r"(b0), "r"(b1));
}

__device__ __forceinline__ void dp4a(int& c, uint32_t a, uint32_t b) {
    asm volatile("dp4a.s32.s32 %0, %1, %2, %0;" : "+r"(c) : "r"(a), "r"(b));
}

__global__ void __launch_bounds__(THREADS, 2)
bmm_i8_kernel(const float* __restrict__ alpha_p, float* __restrict__ out,
              int batch0)
{
    extern __shared__ char smem[];
    const uint32_t sbase = smem_u32(smem);

    const int tid  = threadIdx.x;
    const int wid  = tid >> 5;
    const int lane = tid & 31;
    const int g    = lane >> 2;
    const int tig  = lane & 3;

    // 256 tiles per batch (8 m x 32 n); this launch covers 4 batches
    const int bid   = blockIdx.x;
    const int batch = batch0 + (bid >> 8);
    const int rem   = bid & 255;
    const int m0    = (rem >> 5) * MT;
    const int n0    = (rem & 31) * NT;

    const int8_t* aB = g_a8 + (size_t)batch * MDIM * KDIM + (size_t)m0 * KDIM;
    const int8_t* bB = g_b8 + (size_t)batch * KDIM * NDIM + n0;
    float* outB = out + (size_t)batch * MDIM * NDIM;

    const int wm = wid >> 2;
    const int wn = wid & 3;

    // cp.async indices
    const int ar0 = tid >> 2;
    const int ac0 = (tid & 3) << 4;
    const int br0 = tid >> 3;
    const int bc0 = (tid & 7) << 4;
    // transpose indices
    const int nb  = tid & 31;
    const int kb0 = tid >> 5;

    int cacc[4][4][4];
#pragma unroll
    for (int i = 0; i < 4; i++)
#pragma unroll
        for (int j = 0; j < 4; j++)
#pragma unroll
            for (int r = 0; r < 4; r++) cacc[i][j][r] = 0;

    auto issue_chunk = [&](int chunk, int stg) {
        const int kk = chunk * KT;
        const uint32_t sA = sbase + OFF_A + stg * A_STAGE;
        cpa16(sA + ar0 * A_STRIDE + ac0,        aB + (size_t)ar0 * KDIM + kk + ac0);
        cpa16(sA + (ar0 + 64) * A_STRIDE + ac0, aB + (size_t)(ar0 + 64) * KDIM + kk + ac0);
        const uint32_t sR = sbase + OFF_BRAW + stg * BRAW_STAGE;
        cpa16(sR + br0 * 128 + bc0,        bB + (size_t)(kk + br0) * NDIM + bc0);
        cpa16(sR + (br0 + 32) * 128 + bc0, bB + (size_t)(kk + br0 + 32) * NDIM + bc0);
    };

    auto transposeB = [&](int stg) {
        const uint32_t src = sbase + OFF_BRAW + stg * BRAW_STAGE;
        uint32_t* dst = reinterpret_cast<uint32_t*>(smem + OFF_BT);
#pragma unroll
        for (int t = 0; t < 2; t++) {
            const int kb = kb0 + t * 8;
            const uint32_t rb = src + (uint32_t)(kb * 4) * 128 + nb * 4;
            uint32_t a0 = lds32(rb);
            uint32_t a1 = lds32(rb + 128);
            uint32_t a2 = lds32(rb + 256);
            uint32_t a3 = lds32(rb + 384);
            uint32_t t0 = __byte_perm(a0, a1, 0x5140);
            uint32_t t1 = __byte_perm(a0, a1, 0x7362);
            uint32_t t2 = __byte_perm(a2, a3, 0x5140);
            uint32_t t3 = __byte_perm(a2, a3, 0x7362);
            uint4 v;
            v.x = __byte_perm(t0, t2, 0x5410);
            v.y = __byte_perm(t0, t2, 0x7632);
            v.z = __byte_perm(t1, t3, 0x5410);
            v.w = __byte_perm(t1, t3, 0x7632);
            *reinterpret_cast<uint4*>(dst + kb * B_WORDS + nb * 4) = v;
        }
    };

    // Hybrid compute: tensor pipe takes k[0:32) of the chunk, dp4a on the
    // (otherwise idle) fma/alu pipes takes k[32:64). Both accumulate into the
    // same C fragments: c0,c1 = (row g, cols 2tig,2tig+1); c2,c3 = row g+8.
    auto compute = [&](int stg) {
        const uint32_t baseA = sbase + OFF_A + stg * A_STAGE;
        const uint32_t btBase = sbase + OFF_BT;
        const uint32_t* sb = reinterpret_cast<const uint32_t*>(smem + OFF_BT);
        const int mrow = wm * 64 + (lane & 15);
        const int khl  = lane >> 4;

        // ---- IMMA half: k words 0..7 (k bytes 0..31) ----
        {
            uint32_t af[4][4];
#pragma unroll
            for (int mi = 0; mi < 4; mi++)
                ldmA(af[mi], baseA + (uint32_t)(mrow + mi * 16) * A_STRIDE
                                   + (uint32_t)khl * 16);
            uint32_t bf[4][2];
#pragma unroll
            for (int ni = 0; ni < 4; ni++) {
                const int nl = wn * 32 + ni * 8 + g;
                const int kwb = tig;
                bf[ni][0] = sb[(kwb)     * B_WORDS + nl];
                bf[ni][1] = sb[(kwb + 4) * B_WORDS + nl];
            }
#pragma unroll
            for (int ni = 0; ni < 4; ni++)
#pragma unroll
                for (int mi = 0; mi < 4; mi++)
                    mma_s8(cacc[mi][ni], af[mi], bf[ni][0], bf[ni][1]);
        }

        // ---- dp4a half: k words 8..15 (k bytes 32..63) ----
        const int rA = wm * 64 + g;           // row of c0/c1
        const int cB = wn * 32 + 2 * tig;     // col of c0
#pragma unroll
        for (int kwp = 0; kwp < 4; kwp++) {
            const int kw = 8 + 2 * kwp;
            // A words: rows (rA + mi*16) and (+8), k words kw,kw+1 (LDS.64)
            uint2 aw0[4], aw1[4];
#pragma unroll
            for (int mi = 0; mi < 4; mi++) {
                const uint32_t ra = baseA + (uint32_t)(rA + mi * 16) * A_STRIDE
                                         + (uint32_t)(kw * 4);
                aw0[mi] = lds64(ra);
                aw1[mi] = lds64(ra + 8 * A_STRIDE);
            }
            // B words: rows kw,kw+1 of Bt, cols cB,cB+1 (LDS.64 each row)
            uint2 bwA[4], bwB[4];
#pragma unroll
            for (int ni = 0; ni < 4; ni++) {
                const uint32_t rb = btBase
                    + (uint32_t)(kw * B_WORDS + cB + ni * 8) * 4;
                bwA[ni] = lds64(rb);
                bwB[ni] = lds64(rb + B_WORDS * 4);
            }
#pragma unroll
            for (int mi = 0; mi < 4; mi++)
#pragma unroll
                for (int ni = 0; ni < 4; ni++) {
                    int* c = cacc[mi][ni];
                    dp4a(c[0], aw0[mi].x, bwA[ni].x);
                    dp4a(c[0], aw0[mi].y, bwB[ni].x);
                    dp4a(c[1], aw0[mi].x, bwA[ni].y);
                    dp4a(c[1], aw0[mi].y, bwB[ni].y);
                    dp4a(c[2], aw1[mi].x, bwA[ni].x);
                    dp4a(c[2], aw1[mi].y, bwB[ni].x);
                    dp4a(c[3], aw1[mi].x, bwA[ni].y);
                    dp4a(c[3], aw1[mi].y, bwB[ni].y);
                }
        }
    };

    // ---- prologue: chunks 0 and 1 in flight ----
    issue_chunk(0, 0);
    asm volatile("cp.async.commit_group;" ::: "memory");
    issue_chunk(1, 1);
    asm volatile("cp.async.commit_group;" ::: "memory");

    // ---- mainloop ----
    int stg = 0;
    for (int i = 0; i < KCHUNKS; i++) {
        if (i + 1 < KCHUNKS)
            asm volatile("cp.async.wait_group 1;" ::: "memory");
        else
            asm volatile("cp.async.wait_group 0;" ::: "memory");
        __syncthreads();

        if (i + 2 < KCHUNKS) {
            int fstg = stg + 2; if (fstg >= NSTAGE) fstg -= NSTAGE;
            issue_chunk(i + 2, fstg);
            asm volatile("cp.async.commit_group;" ::: "memory");
        }

        transposeB(stg);
        __syncthreads();
        compute(stg);

        if (++stg == NSTAGE) stg = 0;
    }

    // ---- epilogue ----
    const float alpha = *alpha_p;
#pragma unroll
    for (int mi = 0; mi < 4; mi++) {
#pragma unroll
        for (int ni = 0; ni < 4; ni++) {
            const int row = m0 + wm * 64 + mi * 16 + g;
            const int col = n0 + wn * 32 + ni * 8 + 2 * tig;
            float2 v0, v1;
            v0.x = (float)cacc[mi][ni][0] * alpha;
            v0.y = (float)cacc[mi][ni][1] * alpha;
            v1.x = (float)cacc[mi][ni][2] * alpha;
            v1.y = (float)cacc[mi][ni][3] * alpha;
            *reinterpret_cast<float2*>(outB + (size_t)row * NDIM + col) = v0;
            *reinterpret_cast<float2*>(outB + (size_t)(row + 8) * NDIM + col) = v1;
        }
    }
}

extern "C" void kernel_launch(void* const* d_in, const int* in_sizes, int n_in,
                              void* d_out, int out_size) {
    const int* a32 = (const int*)d_in[0];
    const int* b32 = (const int*)d_in[1];
    const float* alpha = (const float*)(n_in > 2 ? d_in[2] : d_in[1]);
    for (int i = 0; i < n_in; i++) {
        const long long sz = in_sizes[i];
        if (sz == (long long)A_ELEMS)      a32 = (const int*)d_in[i];
        else if (sz == (long long)B_ELEMS) b32 = (const int*)d_in[i];
        else if (sz == 1)                  alpha = (const float*)d_in[i];
    }
    float* out = (float*)d_out;

    int8_t* a8 = nullptr;
    int8_t* b8 = nullptr;
    cudaGetSymbolAddress((void**)&a8, g_a8);
    cudaGetSymbolAddress((void**)&b8, g_b8);

    static int smem_set = 0;
    if (!smem_set) {
        cudaFuncSetAttribute(bmm_i8_kernel,
                             cudaFuncAttributeMaxDynamicSharedMemorySize, SMEM_TOTAL);
        smem_set = 1;
    }

    conv_kernel<<<2048, 256>>>((const int4*)a32, (uint4*)a8, (long)(A_ELEMS / 16));
    conv_kernel<<<2048, 256>>>((const int4*)b32, (uint4*)b8, (long)(B_ELEMS / 16));

    const int grid = 4 * (MDIM / MT) * (NDIM / NT);  // 1024 CTAs per launch
    for (int g = 0; g < 4; g++)
        bmm_i8_kernel<<<grid, THREADS, SMEM_TOTAL>>>(alpha, out, g * 4);
}

// round 10
// speedup vs baseline: 1.4553x; 1.2602x over previous
#include <cuda_runtime.h>
#include <cstdint>

// ---------------------------------------------------------------------------
// BMM_AB_I8_E_F32: C[b,m,n] = alpha * sum_k a[b,m,k]*b[b,k,n]
// B=16, M=1024, K=4096, N=4096.
//
// R2: PTX target sm_103 (no 'a') -> no tcgen05; legacy mma.sync only.
// R6: inputs serialized int32 -> int8 scratch conversion pre-pass.
// R8: legacy IMMA pipe saturates at ~267 MACs/cyc/SM (hard wall).
// R9: hybrid IMMA+dp4a into SHARED accumulators -> pipes serialized on the
//     register dependency (tensor 52.8%, fma 26.3%). dp4a measured rt~1.
// R10: WARP SPECIALIZATION. Warps 0-3: pure IMMA on m[0:64); warps 4-7:
//      pure dp4a on m[64:128). Independent accumulators per warp; tensor and
//      fma pipes overlap across warps on each SMSP.
// ---------------------------------------------------------------------------

#define BATCH   16
#define MDIM    1024
#define KDIM    4096
#define NDIM    4096

#define MT      128
#define NT      128
#define KT      64            // K bytes per pipeline chunk
#define KCHUNKS (KDIM / KT)   // 64
#define THREADS 256
#define NSTAGE  3

#define A_STRIDE 80                     // bytes per m-row in SMEM
#define A_STAGE  (128 * A_STRIDE)       // 10240
#define BRAW_STAGE (64 * 128)           // 8192  raw [k][n] chunk
#define B_WORDS  132                    // transposed k-word row stride (words)
#define BT_BYTES (16 * B_WORDS * 4)     // 8448

#define OFF_A    0
#define OFF_BRAW (NSTAGE * A_STAGE)                 // 30720
#define OFF_BT   (OFF_BRAW + NSTAGE * BRAW_STAGE)   // 55296
#define SMEM_TOTAL (OFF_BT + BT_BYTES)              // 63744

#define A_ELEMS ((size_t)BATCH * MDIM * KDIM)   // 67108864
#define B_ELEMS ((size_t)BATCH * KDIM * NDIM)   // 268435456

__device__ int8_t g_a8[A_ELEMS];
__device__ int8_t g_b8[B_ELEMS];

// ---------------- int32 -> int8 conversion ----------------
__device__ __forceinline__ uint32_t pack4(int4 x) {
    uint32_t lo = __byte_perm((uint32_t)x.x, (uint32_t)x.y, 0x0040);
    uint32_t hi = __byte_perm((uint32_t)x.z, (uint32_t)x.w, 0x0040);
    return __byte_perm(lo, hi, 0x5410);
}

__global__ void __launch_bounds__(256)
conv_kernel(const int4* __restrict__ src, uint4* __restrict__ dst, long n16) {
    const long stride = (long)gridDim.x * blockDim.x;
    for (long i = (long)blockIdx.x * blockDim.x + threadIdx.x; i < n16; i += stride) {
        const int4 x0 = src[i * 4 + 0];
        const int4 x1 = src[i * 4 + 1];
        const int4 x2 = src[i * 4 + 2];
        const int4 x3 = src[i * 4 + 3];
        uint4 v;
        v.x = pack4(x0); v.y = pack4(x1); v.z = pack4(x2); v.w = pack4(x3);
        dst[i] = v;
    }
}

// ---------------- GEMM helpers ----------------
__device__ __forceinline__ uint32_t smem_u32(const void* p) {
    uint32_t a;
    asm("{ .reg .u64 t; cvta.to.shared.u64 t, %1; cvt.u32.u64 %0, t; }"
        : "=r"(a) : "l"(p));
    return a;
}

__device__ __forceinline__ void cpa16(uint32_t dst, const void* src) {
    asm volatile("cp.async.cg.shared.global [%0], [%1], 16;" :: "r"(dst), "l"(src));
}

__device__ __forceinline__ void ldmA(uint32_t a[4], uint32_t addr) {
    asm volatile("ldmatrix.sync.aligned.m8n8.x4.shared.b16 {%0,%1,%2,%3}, [%4];"
                 : "=r"(a[0]), "=r"(a[1]), "=r"(a[2]), "=r"(a[3]) : "r"(addr));
}

__device__ __forceinline__ uint32_t lds32(uint32_t addr) {
    uint32_t v;
    asm volatile("ld.shared.b32 %0, [%1];" : "=r"(v) : "r"(addr));
    return v;
}

__device__ __forceinline__ uint2 lds64(uint32_t addr) {
    uint2 v;
    asm volatile("ld.shared.v2.b32 {%0,%1}, [%2];" : "=r"(v.x), "=r"(v.y) : "r"(addr));
    return v;
}

__device__ __forceinline__ void mma_s8(int c[4], const uint32_t a[4],
                                       uint32_t b0, uint32_t b1) {
    asm volatile(
        "mma.sync.aligned.m16n8k32.row.col.s32.s8.s8.s32 "
        "{%0,%1,%2,%3}, {%4,%5,%6,%7}, {%8,%9}, {%0,%1,%2,%3};"
        : "+r"(c[0]), "+r"(c[1]), "+r"(c[2]), "+r"(c[3])
        : "r"(a[0]), "r"(a[1]), "r"(a[2]), "r"(a[3]), "r"(b0), "r"(b1));
}

__device__ __forceinline__ void dp4a(int& c, uint32_t a, uint32_t b) {
    asm volatile("dp4a.s32.s32 %0, %1, %2, %0;" : "+r"(c) : "r"(a), "r"(b));
}

__global__ void __launch_bounds__(THREADS, 2)
bmm_i8_kernel(const float* __restrict__ alpha_p, float* __restrict__ out,
              int batch0)
{
    extern __shared__ char smem[];
    const uint32_t sbase = smem_u32(smem);

    const int tid  = threadIdx.x;
    const int wid  = tid >> 5;
    const int lane = tid & 31;
    const int g    = lane >> 2;
    const int tig  = lane & 3;

    // 256 tiles per batch (8 m x 32 n); this launch covers 4 batches
    const int bid   = blockIdx.x;
    const int batch = batch0 + (bid >> 8);
    const int rem   = bid & 255;
    const int m0    = (rem >> 5) * MT;
    const int n0    = (rem & 31) * NT;

    const int8_t* aB = g_a8 + (size_t)batch * MDIM * KDIM + (size_t)m0 * KDIM;
    const int8_t* bB = g_b8 + (size_t)batch * KDIM * NDIM + n0;
    float* outB = out + (size_t)batch * MDIM * NDIM;

    // Warp specialization: wid 0-3 = IMMA on m[0:64); wid 4-7 = dp4a on m[64:128).
    // Sub-warp grid 2x2 within each half; warp tile 32m x 64n.
    const int wsub  = wid & 3;
    const int mBase = ((wid < 4) ? 0 : 64) + (wsub >> 1) * 32;
    const int nBase = (wsub & 1) * 64;

    // cp.async indices
    const int ar0 = tid >> 2;
    const int ac0 = (tid & 3) << 4;
    const int br0 = tid >> 3;
    const int bc0 = (tid & 7) << 4;
    // transpose indices
    const int nb  = tid & 31;
    const int kb0 = tid >> 5;

    int cacc[2][8][4];
#pragma unroll
    for (int i = 0; i < 2; i++)
#pragma unroll
        for (int j = 0; j < 8; j++)
#pragma unroll
            for (int r = 0; r < 4; r++) cacc[i][j][r] = 0;

    auto issue_chunk = [&](int chunk, int stg) {
        const int kk = chunk * KT;
        const uint32_t sA = sbase + OFF_A + stg * A_STAGE;
        cpa16(sA + ar0 * A_STRIDE + ac0,        aB + (size_t)ar0 * KDIM + kk + ac0);
        cpa16(sA + (ar0 + 64) * A_STRIDE + ac0, aB + (size_t)(ar0 + 64) * KDIM + kk + ac0);
        const uint32_t sR = sbase + OFF_BRAW + stg * BRAW_STAGE;
        cpa16(sR + br0 * 128 + bc0,        bB + (size_t)(kk + br0) * NDIM + bc0);
        cpa16(sR + (br0 + 32) * 128 + bc0, bB + (size_t)(kk + br0 + 32) * NDIM + bc0);
    };

    auto transposeB = [&](int stg) {
        const uint32_t src = sbase + OFF_BRAW + stg * BRAW_STAGE;
        uint32_t* dst = reinterpret_cast<uint32_t*>(smem + OFF_BT);
#pragma unroll
        for (int t = 0; t < 2; t++) {
            const int kb = kb0 + t * 8;
            const uint32_t rb = src + (uint32_t)(kb * 4) * 128 + nb * 4;
            uint32_t a0 = lds32(rb);
            uint32_t a1 = lds32(rb + 128);
            uint32_t a2 = lds32(rb + 256);
            uint32_t a3 = lds32(rb + 384);
            uint32_t t0 = __byte_perm(a0, a1, 0x5140);
            uint32_t t1 = __byte_perm(a0, a1, 0x7362);
            uint32_t t2 = __byte_perm(a2, a3, 0x5140);
            uint32_t t3 = __byte_perm(a2, a3, 0x7362);
            uint4 v;
            v.x = __byte_perm(t0, t2, 0x5410);
            v.y = __byte_perm(t0, t2, 0x7632);
            v.z = __byte_perm(t1, t3, 0x5410);
            v.w = __byte_perm(t1, t3, 0x7632);
            *reinterpret_cast<uint4*>(dst + kb * B_WORDS + nb * 4) = v;
        }
    };

    // Tensor warps: full K=64 chunk via 32x m16n8k32 (2 mi x 8 ni x 2 ks)
    auto compute_imma = [&](int stg) {
        const uint32_t baseA = sbase + OFF_A + stg * A_STAGE;
        const uint32_t* sb = reinterpret_cast<const uint32_t*>(smem + OFF_BT);
        const int mrow = mBase + (lane & 15);
        const int khl  = lane >> 4;
#pragma unroll
        for (int ks = 0; ks < 2; ks++) {
            uint32_t af[2][4];
#pragma unroll
            for (int mi = 0; mi < 2; mi++)
                ldmA(af[mi], baseA + (uint32_t)(mrow + mi * 16) * A_STRIDE
                                   + (uint32_t)(ks * 2 + khl) * 16);
            uint32_t bf[8][2];
#pragma unroll
            for (int ni = 0; ni < 8; ni++) {
                const int nl = nBase + ni * 8 + g;
                const int kwb = ks * 8 + tig;
                bf[ni][0] = sb[(kwb)     * B_WORDS + nl];
                bf[ni][1] = sb[(kwb + 4) * B_WORDS + nl];
            }
#pragma unroll
            for (int ni = 0; ni < 8; ni++)
#pragma unroll
                for (int mi = 0; mi < 2; mi++)
                    mma_s8(cacc[mi][ni], af[mi], bf[ni][0], bf[ni][1]);
        }
    };

    // dp4a warps: full K=64 chunk on the fma pipe (1024 dp4a/thread/chunk)
    auto compute_dp4a = [&](int stg) {
        const uint32_t baseA = sbase + OFF_A + stg * A_STAGE;
        const uint32_t btBase = sbase + OFF_BT;
        const int rowA0 = mBase + g;
        const int colB0 = nBase + 2 * tig;
#pragma unroll
        for (int kwp = 0; kwp < 8; kwp++) {
            const int kw = 2 * kwp;
            uint2 aw0[2], aw1[2];
#pragma unroll
            for (int mi = 0; mi < 2; mi++) {
                const uint32_t ra = baseA + (uint32_t)(rowA0 + mi * 16) * A_STRIDE
                                         + (uint32_t)(kw * 4);
                aw0[mi] = lds64(ra);
                aw1[mi] = lds64(ra + 8 * A_STRIDE);
            }
#pragma unroll
            for (int nh = 0; nh < 2; nh++) {        // ni in halves: register relief
                uint2 bwA[4], bwB[4];
#pragma unroll
                for (int nj = 0; nj < 4; nj++) {
                    const int ni = nh * 4 + nj;
                    const uint32_t rb = btBase
                        + (uint32_t)(kw * B_WORDS + colB0 + ni * 8) * 4;
                    bwA[nj] = lds64(rb);
                    bwB[nj] = lds64(rb + B_WORDS * 4);
                }
#pragma unroll
                for (int mi = 0; mi < 2; mi++)
#pragma unroll
                    for (int nj = 0; nj < 4; nj++) {
                        int* c = cacc[mi][nh * 4 + nj];
                        dp4a(c[0], aw0[mi].x, bwA[nj].x);
                        dp4a(c[0], aw0[mi].y, bwB[nj].x);
                        dp4a(c[1], aw0[mi].x, bwA[nj].y);
                        dp4a(c[1], aw0[mi].y, bwB[nj].y);
                        dp4a(c[2], aw1[mi].x, bwA[nj].x);
                        dp4a(c[2], aw1[mi].y, bwB[nj].x);
                        dp4a(c[3], aw1[mi].x, bwA[nj].y);
                        dp4a(c[3], aw1[mi].y, bwB[nj].y);
                    }
            }
        }
    };

    // ---- prologue: chunks 0 and 1 in flight ----
    issue_chunk(0, 0);
    asm volatile("cp.async.commit_group;" ::: "memory");
    issue_chunk(1, 1);
    asm volatile("cp.async.commit_group;" ::: "memory");

    // ---- mainloop ----
    int stg = 0;
    for (int i = 0; i < KCHUNKS; i++) {
        if (i + 1 < KCHUNKS)
            asm volatile("cp.async.wait_group 1;" ::: "memory");
        else
            asm volatile("cp.async.wait_group 0;" ::: "memory");
        __syncthreads();

        if (i + 2 < KCHUNKS) {
            int fstg = stg + 2; if (fstg >= NSTAGE) fstg -= NSTAGE;
            issue_chunk(i + 2, fstg);
            asm volatile("cp.async.commit_group;" ::: "memory");
        }

        transposeB(stg);
        __syncthreads();
        if (wid < 4) compute_imma(stg);
        else         compute_dp4a(stg);

        if (++stg == NSTAGE) stg = 0;
    }

    // ---- epilogue: both roles share the m16n8 C-fragment convention ----
    const float alpha = *alpha_p;
#pragma unroll
    for (int mi = 0; mi < 2; mi++) {
#pragma unroll
        for (int ni = 0; ni < 8; ni++) {
            const int row = m0 + mBase + mi * 16 + g;
            const int col = n0 + nBase + ni * 8 + 2 * tig;
            float2 v0, v1;
            v0.x = (float)cacc[mi][ni][0] * alpha;
            v0.y = (float)cacc[mi][ni][1] * alpha;
            v1.x = (float)cacc[mi][ni][2] * alpha;
            v1.y = (float)cacc[mi][ni][3] * alpha;
            *reinterpret_cast<float2*>(outB + (size_t)row * NDIM + col) = v0;
            *reinterpret_cast<float2*>(outB + (size_t)(row + 8) * NDIM + col) = v1;
        }
    }
}

extern "C" void kernel_launch(void* const* d_in, const int* in_sizes, int n_in,
                              void* d_out, int out_size) {
    const int* a32 = (const int*)d_in[0];
    const int* b32 = (const int*)d_in[1];
    const float* alpha = (const float*)(n_in > 2 ? d_in[2] : d_in[1]);
    for (int i = 0; i < n_in; i++) {
        const long long sz = in_sizes[i];
        if (sz == (long long)A_ELEMS)      a32 = (const int*)d_in[i];
        else if (sz == (long long)B_ELEMS) b32 = (const int*)d_in[i];
        else if (sz == 1)                  alpha = (const float*)d_in[i];
    }
    float* out = (float*)d_out;

    int8_t* a8 = nullptr;
    int8_t* b8 = nullptr;
    cudaGetSymbolAddress((void**)&a8, g_a8);
    cudaGetSymbolAddress((void**)&b8, g_b8);

    static int smem_set = 0;
    if (!smem_set) {
        cudaFuncSetAttribute(bmm_i8_kernel,
                             cudaFuncAttributeMaxDynamicSharedMemorySize, SMEM_TOTAL);
        smem_set = 1;
    }

    conv_kernel<<<2048, 256>>>((const int4*)a32, (uint4*)a8, (long)(A_ELEMS / 16));
    conv_kernel<<<2048, 256>>>((const int4*)b32, (uint4*)b8, (long)(B_ELEMS / 16));

    const int grid = 4 * (MDIM / MT) * (NDIM / NT);  // 1024 CTAs per launch
    for (int g = 0; g < 4; g++)
        bmm_i8_kernel<<<grid, THREADS, SMEM_TOTAL>>>(alpha, out, g * 4);
}